// round 14
// baseline (speedup 1.0000x reference)
#include <cuda_runtime.h>
#include <cstdint>

// ---------------------------------------------------------------------------
// BatchTopK via exact threshold selection on float bit patterns. 4 kernels:
//   k_main:    proven streaming loop (78us @ 79% DRAM) — byte-identical.
//   k_scan:    1 block, shfl suffix scan -> B*, c_above, k_total, need_full;
//              self-cleans g_hist_hi in place (each thread zeroes the bins it
//              just read).
//   k_scatter: slab walk (parallel loads): bin>B* -> out, boundary -> buffer
//              (+ inline 512-bin level-1 refinement hist gh1).
//   k_refine:  1 block: register-caches the boundary buffer (1 global pass),
//              refines exact threshold bits; ties kept by smallest index via
//              O(tcnt^2) rank selection. Guarded exact full fallback.
//              Cleans gh1/g_nb at the end (graph is self-cleaning).
// No __threadfence / tickets; no global atomics in k_main's hot path.
// ---------------------------------------------------------------------------

#define T_DET      3.0f
#define NBINS_HI   8192
#define NBINS      16384
#define SLAB       16
#define NUM_WARPS  65536
#define BND_CAP    (1u << 20)
#define TIE_CAP    4096
#define RC         8            // register-cache entries per thread (8*1024)

__device__ unsigned g_hist_hi[NBINS_HI];
__device__ unsigned g_hist2[NBINS];     // fallback only
__device__ unsigned gh1[512];           // level-1 refinement hist (bits[16:8])
__device__ int      g_B_star;
__device__ unsigned g_c_above;
__device__ unsigned g_k_total;
__device__ int      g_need_full;
__device__ unsigned g_nb;
__device__ unsigned g_warp_cnt[NUM_WARPS];
__device__ uint2    g_cand[(size_t)NUM_WARPS * SLAB];
__device__ unsigned g_bnd_bits[BND_CAP];
__device__ unsigned g_bnd_idx[BND_CAP];

__device__ __forceinline__ void handle4(float4 a, int i4, unsigned* sh,
                                        unsigned* wctr, uint2* slab) {
    float vals[4] = {a.x, a.y, a.z, a.w};
#pragma unroll
    for (int j = 0; j < 4; j++) {
        if (vals[j] >= T_DET) {
            unsigned u = __float_as_uint(vals[j]);
            atomicAdd(&sh[(u >> 17) - NBINS_HI], 1u);
            unsigned pos = atomicAdd(wctr, 1u);
            if (pos < SLAB) slab[pos] = make_uint2(u, (unsigned)(4 * i4 + j));
        }
    }
}

// Proven streaming loop + branch-only smem hist (UNCHANGED).
__global__ void __launch_bounds__(1024, 1)
k_main(const float4* __restrict__ x4, float4* __restrict__ o4, int n4, int ntiles) {
    __shared__ unsigned sh[NBINS_HI];
    __shared__ unsigned wcnt[32];
    for (int b = threadIdx.x; b < NBINS_HI; b += 1024) sh[b] = 0u;
    if (threadIdx.x < 32) wcnt[threadIdx.x] = 0u;
    __syncthreads();

    const int lane   = threadIdx.x & 31;
    const int wlocal = threadIdx.x >> 5;
    const int W      = blockIdx.x * 32 + wlocal;
    const int NW     = gridDim.x * 32;
    uint2*    slab   = g_cand + (size_t)W * SLAB;
    unsigned* wctr   = &wcnt[wlocal];
    const float4 z4  = make_float4(0.f, 0.f, 0.f, 0.f);

    for (int tile = W; tile < ntiles; tile += NW) {
        const int base = tile * 256;
        if (base + 256 <= n4) {
            float4 v[8];
#pragma unroll
            for (int it = 0; it < 8; it++) v[it] = x4[base + it * 32 + lane];
#pragma unroll
            for (int it = 0; it < 8; it++) o4[base + it * 32 + lane] = z4;
#pragma unroll
            for (int p = 0; p < 4; p++) {
                float4 a = v[2 * p], b = v[2 * p + 1];
                float m = fmaxf(fmaxf(fmaxf(a.x, a.y), fmaxf(a.z, a.w)),
                                fmaxf(fmaxf(b.x, b.y), fmaxf(b.z, b.w)));
                if (m >= T_DET) {
                    handle4(a, base + (2 * p) * 32 + lane, sh, wctr, slab);
                    handle4(b, base + (2 * p + 1) * 32 + lane, sh, wctr, slab);
                }
            }
        } else {
            for (int it = 0; it < 8; it++) {
                int i4 = base + it * 32 + lane;
                if (i4 < n4) {
                    float4 a = x4[i4];
                    o4[i4] = z4;
                    handle4(a, i4, sh, wctr, slab);
                }
            }
        }
    }
    __syncwarp();
    if (lane == 0) g_warp_cnt[W] = wcnt[wlocal];

    __syncthreads();
    for (int b = threadIdx.x; b < NBINS_HI; b += 1024) {
        unsigned c = sh[b];
        if (c) atomicAdd(&g_hist_hi[b], c);
    }
}

// Single block, shfl suffix scan -> threshold bin; zeroes hist in place.
__global__ void __launch_bounds__(1024, 1)
k_scan(const int* __restrict__ kptr, int n) {
    __shared__ unsigned wtot[32];
    __shared__ unsigned wexc[32];
    __shared__ int s_any;
    int t = threadIdx.x, lane = t & 31, wid = t >> 5;

    unsigned batch = (unsigned)(n >> 16);   // d_sae = 65536
    unsigned K = (unsigned)(*kptr) * batch;
    if (t == 0) { g_k_total = K; s_any = 0; }

    const int C = NBINS_HI / 1024;   // 8
    unsigned h[C];
    unsigned a = 0;
#pragma unroll
    for (int jj = 0; jj < C; jj++) {
        h[jj] = g_hist_hi[t * C + jj];
        g_hist_hi[t * C + jj] = 0u;          // self-clean for next replay
        a += h[jj];
    }

    unsigned x = a;
#pragma unroll
    for (int off = 1; off < 32; off <<= 1) {
        unsigned y = __shfl_down_sync(0xFFFFFFFFu, x, off);
        if (lane + off < 32) x += y;
    }
    if (lane == 0) wtot[wid] = x;
    __syncthreads();
    if (wid == 0) {
        unsigned w = wtot[lane];
        unsigned xs = w;
#pragma unroll
        for (int off = 1; off < 32; off <<= 1) {
            unsigned y = __shfl_down_sync(0xFFFFFFFFu, xs, off);
            if (lane + off < 32) xs += y;
        }
        wexc[lane] = xs - w;
    }
    __syncthreads();

    unsigned running = (x + wexc[wid]) - a;
    int found = 0;
#pragma unroll
    for (int jj = C - 1; jj >= 0; --jj) {
        if (running < K && running + h[jj] >= K) {
            g_B_star = NBINS_HI + t * C + jj;
            g_c_above = running;
            found = 1;
        }
        running += h[jj];
    }
    if (found) s_any = 1;
    __syncthreads();
    if (t == 0) g_need_full = !s_any;
}

// Slab walk (parallel loads): winners -> out; boundary -> buffer + gh1.
__global__ void __launch_bounds__(1024, 1)
k_scatter(float* __restrict__ out, int nwarps) {
    if (g_need_full) return;
    const int B = g_B_star;
    int nslots = nwarps * SLAB;
    int stride = gridDim.x * blockDim.x;
    for (int s = blockIdx.x * blockDim.x + threadIdx.x; s < nslots; s += stride) {
        int w = s >> 4;                       // SLAB == 16
        int e = s & 15;
        unsigned cnt = g_warp_cnt[w];
        uint2 c = g_cand[s];
        if (e == 0 && cnt > SLAB) g_need_full = 1;
        if ((unsigned)e < min(cnt, (unsigned)SLAB)) {
            int bin = (int)(c.x >> 17);
            if (bin > B) {
                out[c.y] = __uint_as_float(c.x);
            } else if (bin == B) {
                unsigned p = atomicAdd(&g_nb, 1u);
                if (p < BND_CAP) {
                    g_bnd_bits[p] = c.x; g_bnd_idx[p] = c.y;
                    atomicAdd(&gh1[(c.x >> 8) & 0x1FFu], 1u);
                } else g_need_full = 1;
            }
        }
    }
}

// Low-barrier crossing-finder over NB (<=1024, mult of 32) bins in s_h.
__device__ void find_cross(const unsigned* s_h, int NB, unsigned m,
                           int* o_bin, unsigned* o_above) {
    __shared__ unsigned wtot[32];
    __shared__ unsigned wexc[32];
    int t = threadIdx.x, lane = t & 31, wid = t >> 5;
    unsigned a = (t < NB) ? s_h[t] : 0u;
    unsigned x = a;
#pragma unroll
    for (int off = 1; off < 32; off <<= 1) {
        unsigned y = __shfl_down_sync(0xFFFFFFFFu, x, off);
        if (lane + off < 32) x += y;
    }
    if (lane == 0 && wid < 32) wtot[wid] = (t < NB) ? x : 0u;
    __syncthreads();
    if (wid == 0) {
        unsigned w = wtot[lane];
        unsigned xs = w;
#pragma unroll
        for (int off = 1; off < 32; off <<= 1) {
            unsigned y = __shfl_down_sync(0xFFFFFFFFu, xs, off);
            if (lane + off < 32) xs += y;
        }
        wexc[lane] = xs - w;
    }
    __syncthreads();
    if (t < NB) {
        unsigned incl = x + wexc[wid];
        unsigned above = incl - a;
        if (above < m && incl >= m) { *o_bin = t; *o_above = above; }
    }
    __syncthreads();
}

// Block-wide refine+tie over the boundary buffer, register-cached (1 pass).
__device__ void sel2_body(float* __restrict__ out, bool use_gh1) {
    __shared__ unsigned h1[512];
    __shared__ unsigned h2[256];
    __shared__ unsigned tie_idx[TIE_CAP];
    __shared__ unsigned s_tcnt;
    __shared__ int s_s1;
    __shared__ unsigned s_c1;
    __shared__ int s_b2;
    __shared__ unsigned s_c2;
    __shared__ int s_mode;

    int t = threadIdx.x;
    unsigned nb = min(g_nb, (unsigned)BND_CAP);
    int B = g_B_star;
    unsigned K = g_k_total, ca = g_c_above;

    if (t == 0) {
        if (nb == 0u || ca >= K) s_mode = 2;
        else s_mode = ((K - ca) >= nb) ? 1 : 0;
    }
    __syncthreads();
    if (s_mode == 2) return;

    // ---- register cache: one global pass over the boundary buffer ----
    unsigned cb[RC], ci[RC];
    int nc = 0;
#pragma unroll
    for (int k2 = 0; k2 < RC; k2++) {
        unsigned i = (unsigned)t + (unsigned)k2 * 1024u;
        if (i < nb) { cb[k2] = g_bnd_bits[i]; ci[k2] = g_bnd_idx[i]; nc = k2 + 1; }
    }
    const unsigned spill_start = RC * 1024u;   // rare: nb > 8192

    if (s_mode == 1) {   // accept every boundary candidate
#pragma unroll
        for (int k2 = 0; k2 < RC; k2++)
            if (k2 < nc) out[ci[k2]] = __uint_as_float(cb[k2]);
        for (unsigned i = spill_start + t; i < nb; i += 1024)
            out[g_bnd_idx[i]] = __uint_as_float(g_bnd_bits[i]);
        return;
    }
    unsigned m = K - ca;

    // level-1 hist (pre-built by k_scatter on the normal path)
    if (use_gh1) {
        if (t < 512) h1[t] = gh1[t];
        __syncthreads();
    } else {
        if (t < 512) h1[t] = 0u;
        __syncthreads();
#pragma unroll
        for (int k2 = 0; k2 < RC; k2++)
            if (k2 < nc) atomicAdd(&h1[(cb[k2] >> 8) & 0x1FFu], 1u);
        for (unsigned i = spill_start + t; i < nb; i += 1024)
            atomicAdd(&h1[(g_bnd_bits[i] >> 8) & 0x1FFu], 1u);
        __syncthreads();
    }
    find_cross(h1, 512, m, &s_s1, &s_c1);
    int s1 = s_s1; unsigned c1 = s_c1;

    // level-2 hist from the register cache
    if (t < 256) h2[t] = 0u;
    __syncthreads();
#pragma unroll
    for (int k2 = 0; k2 < RC; k2++)
        if (k2 < nc && ((cb[k2] >> 8) & 0x1FFu) == (unsigned)s1)
            atomicAdd(&h2[cb[k2] & 0xFFu], 1u);
    for (unsigned i = spill_start + t; i < nb; i += 1024) {
        unsigned bits = g_bnd_bits[i];
        if (((bits >> 8) & 0x1FFu) == (unsigned)s1)
            atomicAdd(&h2[bits & 0xFFu], 1u);
    }
    __syncthreads();
    find_cross(h2, 256, m - c1, &s_b2, &s_c2);
    unsigned Tb = ((unsigned)B << 17) | ((unsigned)s1 << 8) | (unsigned)s_b2;
    unsigned r  = (m - c1) - s_c2;
    if (t == 0) s_tcnt = 0u;
    __syncthreads();

    // winners + tie gather, from the register cache
#pragma unroll
    for (int k2 = 0; k2 < RC; k2++) {
        if (k2 < nc) {
            unsigned bits = cb[k2];
            if (bits > Tb) {
                out[ci[k2]] = __uint_as_float(bits);
            } else if (bits == Tb) {
                unsigned p = atomicAdd(&s_tcnt, 1u);
                if (p < TIE_CAP) tie_idx[p] = ci[k2];
            }
        }
    }
    for (unsigned i = spill_start + t; i < nb; i += 1024) {
        unsigned bits = g_bnd_bits[i];
        if (bits > Tb) {
            out[g_bnd_idx[i]] = __uint_as_float(bits);
        } else if (bits == Tb) {
            unsigned p = atomicAdd(&s_tcnt, 1u);
            if (p < TIE_CAP) tie_idx[p] = g_bnd_idx[i];
        }
    }
    __syncthreads();
    unsigned tcnt = min(s_tcnt, (unsigned)TIE_CAP);
    if (r >= tcnt) {
        for (unsigned i = t; i < tcnt; i += blockDim.x)
            out[tie_idx[i]] = __uint_as_float(Tb);
        return;
    }
    // keep the r smallest indices among tcnt ties (O(tcnt^2), tcnt tiny)
    for (unsigned i = t; i < tcnt; i += blockDim.x) {
        unsigned my = tie_idx[i];
        unsigned rank = 0;
        for (unsigned j2 = 0; j2 < tcnt; j2++)
            rank += (tie_idx[j2] < my) ? 1u : 0u;
        if (rank < r) out[my] = __uint_as_float(Tb);
    }
}

// Single block: refinement (or guarded exact fallback), then state cleanup.
__global__ void __launch_bounds__(1024, 1)
k_refine(const float4* __restrict__ x4, float* __restrict__ out, int n4) {
    int t = threadIdx.x;
    if (g_need_full) {
        unsigned K = g_k_total;
        if (t == 0) g_nb = 0u;
        __syncthreads();
        if (K > 0u) {
            for (int i = t; i < n4; i += 1024) {
                float4 v = x4[i];
                float vals[4] = {v.x, v.y, v.z, v.w};
#pragma unroll
                for (int j = 0; j < 4; j++)
                    if (vals[j] > 0.0f)
                        atomicAdd(&g_hist2[__float_as_uint(vals[j]) >> 17], 1u);
            }
            __syncthreads();

            __shared__ unsigned s_arr[1024];
            __shared__ int s_found;
            const int C = NBINS / 1024;
            unsigned h[C];
            unsigned a = 0;
            if (t == 0) s_found = 0;
            __syncthreads();
#pragma unroll
            for (int jj = 0; jj < C; jj++) { h[jj] = g_hist2[t * C + jj]; a += h[jj]; }
            s_arr[t] = a;
            __syncthreads();
            for (int off = 1; off < 1024; off <<= 1) {
                unsigned v = (t + off < 1024) ? s_arr[t + off] : 0u;
                __syncthreads();
                s_arr[t] += v;
                __syncthreads();
            }
            unsigned running = s_arr[t] - a;
#pragma unroll
            for (int jj = C - 1; jj >= 0; --jj) {
                if (running < K && running + h[jj] >= K) {
                    g_B_star = t * C + jj;
                    g_c_above = running;
                    s_found = 1;
                }
                running += h[jj];
            }
            __syncthreads();
            if (t == 0 && !s_found) { g_B_star = -1; g_c_above = s_arr[0]; }
            __syncthreads();

            int B = g_B_star;
            for (int i = t; i < n4; i += 1024) {
                float4 v = x4[i];
                float vals[4] = {v.x, v.y, v.z, v.w};
#pragma unroll
                for (int j = 0; j < 4; j++) {
                    float val = vals[j];
                    if (val > 0.0f) {
                        unsigned u = __float_as_uint(val);
                        int bin = (int)(u >> 17);
                        if (bin > B) {
                            out[4 * i + j] = val;
                        } else if (bin == B) {
                            unsigned p = atomicAdd(&g_nb, 1u);
                            if (p < BND_CAP) { g_bnd_bits[p] = u; g_bnd_idx[p] = (unsigned)(4 * i + j); }
                        }
                    }
                }
            }
            __syncthreads();
            sel2_body(out, false);
            __syncthreads();
            for (int i = t; i < NBINS; i += 1024) g_hist2[i] = 0u;
            for (int i = t; i < NBINS_HI; i += 1024) g_hist_hi[i] = 0u;
        }
    } else {
        sel2_body(out, true);
        __syncthreads();
    }
    // ---- self-cleaning for the next graph replay ----
    if (t < 512) gh1[t] = 0u;
    if (t == 0) g_nb = 0u;
}

extern "C" void kernel_launch(void* const* d_in, const int* in_sizes, int n_in,
                              void* d_out, int out_size) {
    const float* x    = (const float*)d_in[0];
    const int*   kptr = (const int*)d_in[1];
    float*       out  = (float*)d_out;
    int n  = in_sizes[0];
    int n4 = n >> 2;

    int ntiles = (n4 + 255) / 256;
    int main_blocks = (ntiles + 31) / 32;
    if (main_blocks > NUM_WARPS / 32) main_blocks = NUM_WARPS / 32;
    int nwarps = main_blocks * 32;

    k_main<<<main_blocks, 1024>>>((const float4*)x, (float4*)out, n4, ntiles);
    k_scan<<<1, 1024>>>(kptr, n);
    k_scatter<<<512, 1024>>>(out, nwarps);
    k_refine<<<1, 1024>>>((const float4*)x, out, n4);
}

// round 15
// speedup vs baseline: 1.3223x; 1.3223x over previous
#include <cuda_runtime.h>
#include <cstdint>

// ---------------------------------------------------------------------------
// BatchTopK via exact threshold selection on float bit patterns. 4 kernels:
//   k_main:    proven streaming loop: read x, out=0, detect >= 3.0,
//              candidates -> per-warp global slabs + SMEM hist in the rare
//              branch. Hist: 8192 FINE bins over [2.0,8.0) (bits>>11), plus
//              c8 counter for >= 8.0 (boundary bin shrinks to ~200 entries).
//   k_scan:    1 block, shfl suffix scan (seeded with c8) -> B*, c_above,
//              k_total; need_full if threshold outside [2,8) coverage.
//   k_scatter: slab walk (parallel loads): bin>B* -> out, boundary -> buffer
//              (+ inline 256-bin level-1 refinement hist gh1).
//   k_refine:  1 block: exact threshold bits (shift-parameterized two-level
//              refinement); ties kept by smallest index via O(tcnt^2) rank
//              selection. Guarded exact full-range fallback (bits>>17 keys).
//              Self-cleans all scratch state at the end.
// No __threadfence / tickets; no global atomics in k_main's hot path.
// ---------------------------------------------------------------------------

#define T_DET      3.0f
#define NBINS_HI   8192     // fine bins: (bits>>11) - 0x80000, range [2.0,8.0)
#define BIN_BASE   0x80000u // 0x40000000 >> 11
#define BITS_8     0x41000000u
#define NBINS      16384    // fallback bins: bits>>17 over all positives
#define SLAB       16
#define NUM_WARPS  65536
#define BND_CAP    (1u << 20)
#define TIE_CAP    4096

__device__ unsigned g_hist_hi[NBINS_HI];
__device__ unsigned g_hist2[NBINS];     // fallback only
__device__ unsigned gh1[512];           // level-1 refinement hist
__device__ unsigned g_c8;               // count of candidates >= 8.0
__device__ int      g_B_star;           // absolute key (bits>>11), or bits>>17 in fallback
__device__ unsigned g_c_above;
__device__ unsigned g_k_total;
__device__ int      g_need_full;
__device__ unsigned g_nb;
__device__ unsigned g_warp_cnt[NUM_WARPS];
__device__ uint2    g_cand[(size_t)NUM_WARPS * SLAB];
__device__ unsigned g_bnd_bits[BND_CAP];
__device__ unsigned g_bnd_idx[BND_CAP];

__device__ __forceinline__ void handle4(float4 a, int i4, unsigned* sh,
                                        unsigned* sc8, unsigned* wctr, uint2* slab) {
    float vals[4] = {a.x, a.y, a.z, a.w};
#pragma unroll
    for (int j = 0; j < 4; j++) {
        if (vals[j] >= T_DET) {
            unsigned u = __float_as_uint(vals[j]);
            if (u < BITS_8) atomicAdd(&sh[(u >> 11) - BIN_BASE], 1u);
            else            atomicAdd(sc8, 1u);
            unsigned pos = atomicAdd(wctr, 1u);
            if (pos < SLAB) slab[pos] = make_uint2(u, (unsigned)(4 * i4 + j));
        }
    }
}

// Proven streaming loop + branch-only smem hist.
__global__ void __launch_bounds__(1024, 1)
k_main(const float4* __restrict__ x4, float4* __restrict__ o4, int n4, int ntiles) {
    __shared__ unsigned sh[NBINS_HI];
    __shared__ unsigned wcnt[32];
    __shared__ unsigned s_c8;
    for (int b = threadIdx.x; b < NBINS_HI; b += 1024) sh[b] = 0u;
    if (threadIdx.x < 32) wcnt[threadIdx.x] = 0u;
    if (threadIdx.x == 0) s_c8 = 0u;
    __syncthreads();

    const int lane   = threadIdx.x & 31;
    const int wlocal = threadIdx.x >> 5;
    const int W      = blockIdx.x * 32 + wlocal;
    const int NW     = gridDim.x * 32;
    uint2*    slab   = g_cand + (size_t)W * SLAB;
    unsigned* wctr   = &wcnt[wlocal];
    const float4 z4  = make_float4(0.f, 0.f, 0.f, 0.f);

    for (int tile = W; tile < ntiles; tile += NW) {
        const int base = tile * 256;
        if (base + 256 <= n4) {
            float4 v[8];
#pragma unroll
            for (int it = 0; it < 8; it++) v[it] = x4[base + it * 32 + lane];
#pragma unroll
            for (int it = 0; it < 8; it++) o4[base + it * 32 + lane] = z4;
#pragma unroll
            for (int p = 0; p < 4; p++) {
                float4 a = v[2 * p], b = v[2 * p + 1];
                float m = fmaxf(fmaxf(fmaxf(a.x, a.y), fmaxf(a.z, a.w)),
                                fmaxf(fmaxf(b.x, b.y), fmaxf(b.z, b.w)));
                if (m >= T_DET) {
                    handle4(a, base + (2 * p) * 32 + lane, sh, &s_c8, wctr, slab);
                    handle4(b, base + (2 * p + 1) * 32 + lane, sh, &s_c8, wctr, slab);
                }
            }
        } else {
            for (int it = 0; it < 8; it++) {
                int i4 = base + it * 32 + lane;
                if (i4 < n4) {
                    float4 a = x4[i4];
                    o4[i4] = z4;
                    handle4(a, i4, sh, &s_c8, wctr, slab);
                }
            }
        }
    }
    __syncwarp();
    if (lane == 0) g_warp_cnt[W] = wcnt[wlocal];

    __syncthreads();
    for (int b = threadIdx.x; b < NBINS_HI; b += 1024) {
        unsigned c = sh[b];
        if (c) atomicAdd(&g_hist_hi[b], c);
    }
    if (threadIdx.x == 0 && s_c8) atomicAdd(&g_c8, s_c8);
}

// Single block, shfl suffix scan over 8192 fine bins -> threshold bin.
__global__ void __launch_bounds__(1024, 1)
k_scan(const int* __restrict__ kptr, int n) {
    __shared__ unsigned wtot[32];
    __shared__ unsigned wexc[32];
    __shared__ int s_any;
    int t = threadIdx.x, lane = t & 31, wid = t >> 5;

    unsigned batch = (unsigned)(n >> 16);   // d_sae = 65536
    unsigned K = (unsigned)(*kptr) * batch;
    unsigned c8 = g_c8;                      // candidates >= 8.0 (above range)
    if (t == 0) { g_k_total = K; s_any = 0; }

    const int C = NBINS_HI / 1024;   // 8
    unsigned h[C];
    unsigned a = 0;
#pragma unroll
    for (int jj = 0; jj < C; jj++) { h[jj] = g_hist_hi[t * C + jj]; a += h[jj]; }

    unsigned x = a;
#pragma unroll
    for (int off = 1; off < 32; off <<= 1) {
        unsigned y = __shfl_down_sync(0xFFFFFFFFu, x, off);
        if (lane + off < 32) x += y;
    }
    if (lane == 0) wtot[wid] = x;
    __syncthreads();
    if (wid == 0) {
        unsigned w = wtot[lane];
        unsigned xs = w;
#pragma unroll
        for (int off = 1; off < 32; off <<= 1) {
            unsigned y = __shfl_down_sync(0xFFFFFFFFu, xs, off);
            if (lane + off < 32) xs += y;
        }
        wexc[lane] = xs - w;
    }
    __syncthreads();

    unsigned running = (x + wexc[wid]) - a + c8;   // seed with >=8.0 count
    int found = 0;
#pragma unroll
    for (int jj = C - 1; jj >= 0; --jj) {
        if (running < K && running + h[jj] >= K) {
            g_B_star = (int)(BIN_BASE + (unsigned)(t * C + jj));  // absolute key
            g_c_above = running;
            found = 1;
        }
        running += h[jj];
    }
    if (found) s_any = 1;
    __syncthreads();
    if (t == 0) g_need_full = !s_any;
}

// Slab walk (parallel loads): winners -> out; boundary -> buffer + gh1.
__global__ void __launch_bounds__(1024, 1)
k_scatter(float* __restrict__ out, int nwarps) {
    if (g_need_full) return;
    const int B = g_B_star;                  // key space: bits>>11
    int nslots = nwarps * SLAB;
    int stride = gridDim.x * blockDim.x;
    for (int s = blockIdx.x * blockDim.x + threadIdx.x; s < nslots; s += stride) {
        int w = s >> 4;                       // SLAB == 16
        int e = s & 15;
        unsigned cnt = g_warp_cnt[w];
        uint2 c = g_cand[s];
        if (e == 0 && cnt > SLAB) g_need_full = 1;
        if ((unsigned)e < min(cnt, (unsigned)SLAB)) {
            int bin = (int)(c.x >> 11);
            if (bin > B) {
                out[c.y] = __uint_as_float(c.x);
            } else if (bin == B) {
                unsigned p = atomicAdd(&g_nb, 1u);
                if (p < BND_CAP) {
                    g_bnd_bits[p] = c.x; g_bnd_idx[p] = c.y;
                    atomicAdd(&gh1[(c.x >> 3) & 0xFFu], 1u);   // bits[10:3]
                } else g_need_full = 1;
            }
        }
    }
}

// Low-barrier crossing-finder over NB (<=1024) bins in s_h.
__device__ void find_cross(const unsigned* s_h, int NB, unsigned m,
                           int* o_bin, unsigned* o_above) {
    __shared__ unsigned wtot[32];
    __shared__ unsigned wexc[32];
    int t = threadIdx.x, lane = t & 31, wid = t >> 5;
    unsigned a = (t < NB) ? s_h[t] : 0u;
    unsigned x = a;
#pragma unroll
    for (int off = 1; off < 32; off <<= 1) {
        unsigned y = __shfl_down_sync(0xFFFFFFFFu, x, off);
        if (lane + off < 32) x += y;
    }
    if (lane == 0 && wid < 32) wtot[wid] = (t < NB) ? x : 0u;
    __syncthreads();
    if (wid == 0) {
        unsigned w = wtot[lane];
        unsigned xs = w;
#pragma unroll
        for (int off = 1; off < 32; off <<= 1) {
            unsigned y = __shfl_down_sync(0xFFFFFFFFu, xs, off);
            if (lane + off < 32) xs += y;
        }
        wexc[lane] = xs - w;
    }
    __syncthreads();
    if (t < NB) {
        unsigned incl = x + wexc[wid];
        unsigned above = incl - a;
        if (above < m && incl >= m) { *o_bin = t; *o_above = above; }
    }
    __syncthreads();
}

// Block-wide refine+tie over the boundary buffer. Key = bits>>S.
// Level-1: 256 bins on bits[S-1:S-8]; level-2: (1<<(S-8)) bins on low bits.
__device__ void sel2_body(float* __restrict__ out, bool use_gh1, int S) {
    __shared__ unsigned h1[256];
    __shared__ unsigned h2[512];
    __shared__ unsigned tie_idx[TIE_CAP];
    __shared__ unsigned s_tcnt;
    __shared__ int s_s1;
    __shared__ unsigned s_c1;
    __shared__ int s_b2;
    __shared__ unsigned s_c2;
    __shared__ int s_mode;

    int t = threadIdx.x;
    unsigned nb = min(g_nb, (unsigned)BND_CAP);
    int B = g_B_star;
    unsigned K = g_k_total, ca = g_c_above;
    const int S2 = S - 8;                // low bits for level-2
    const int NB2 = 1 << S2;
    const unsigned M2 = (unsigned)NB2 - 1u;

    if (t == 0) {
        if (nb == 0u || ca >= K) s_mode = 2;
        else s_mode = ((K - ca) >= nb) ? 1 : 0;
    }
    __syncthreads();
    if (s_mode == 2) return;
    if (s_mode == 1) {
        for (unsigned i = t; i < nb; i += blockDim.x)
            out[g_bnd_idx[i]] = __uint_as_float(g_bnd_bits[i]);
        return;
    }
    unsigned m = K - ca;

    if (use_gh1) {
        if (t < 256) h1[t] = gh1[t];
        __syncthreads();
    } else {
        if (t < 256) h1[t] = 0u;
        __syncthreads();
        for (unsigned i = t; i < nb; i += blockDim.x)
            atomicAdd(&h1[(g_bnd_bits[i] >> S2) & 0xFFu], 1u);
        __syncthreads();
    }
    find_cross(h1, 256, m, &s_s1, &s_c1);
    int s1 = s_s1; unsigned c1 = s_c1;

    if (t < NB2) h2[t] = 0u;
    __syncthreads();
    for (unsigned i = t; i < nb; i += blockDim.x) {
        unsigned bits = g_bnd_bits[i];
        if (((bits >> S2) & 0xFFu) == (unsigned)s1)
            atomicAdd(&h2[bits & M2], 1u);
    }
    __syncthreads();
    find_cross(h2, NB2, m - c1, &s_b2, &s_c2);
    unsigned Tb = ((unsigned)B << S) | ((unsigned)s1 << S2) | (unsigned)s_b2;
    unsigned r  = (m - c1) - s_c2;
    if (t == 0) s_tcnt = 0u;
    __syncthreads();

    for (unsigned i = t; i < nb; i += blockDim.x) {
        unsigned bits = g_bnd_bits[i];
        if (bits > Tb) {
            out[g_bnd_idx[i]] = __uint_as_float(bits);
        } else if (bits == Tb) {
            unsigned p = atomicAdd(&s_tcnt, 1u);
            if (p < TIE_CAP) tie_idx[p] = g_bnd_idx[i];
        }
    }
    __syncthreads();
    unsigned tcnt = min(s_tcnt, (unsigned)TIE_CAP);
    if (r >= tcnt) {
        for (unsigned i = t; i < tcnt; i += blockDim.x)
            out[tie_idx[i]] = __uint_as_float(Tb);
        return;
    }
    // keep the r smallest indices among tcnt ties (O(tcnt^2), tcnt tiny)
    for (unsigned i = t; i < tcnt; i += blockDim.x) {
        unsigned my = tie_idx[i];
        unsigned rank = 0;
        for (unsigned j2 = 0; j2 < tcnt; j2++)
            rank += (tie_idx[j2] < my) ? 1u : 0u;
        if (rank < r) out[my] = __uint_as_float(Tb);
    }
}

// Single block: refinement (or guarded exact fallback), then state cleanup.
__global__ void __launch_bounds__(1024, 1)
k_refine(const float4* __restrict__ x4, float* __restrict__ out, int n4) {
    int t = threadIdx.x;
    if (g_need_full) {
        unsigned K = g_k_total;
        if (t == 0) g_nb = 0u;   // discard partial boundary entries
        __syncthreads();
        if (K > 0u) {
            for (int i = t; i < n4; i += 1024) {
                float4 v = x4[i];
                float vals[4] = {v.x, v.y, v.z, v.w};
#pragma unroll
                for (int j = 0; j < 4; j++)
                    if (vals[j] > 0.0f)
                        atomicAdd(&g_hist2[__float_as_uint(vals[j]) >> 17], 1u);
            }
            __syncthreads();

            __shared__ unsigned s_arr[1024];
            __shared__ int s_found;
            const int C = NBINS / 1024;
            unsigned h[C];
            unsigned a = 0;
            if (t == 0) s_found = 0;
            __syncthreads();
#pragma unroll
            for (int jj = 0; jj < C; jj++) { h[jj] = g_hist2[t * C + jj]; a += h[jj]; }
            s_arr[t] = a;
            __syncthreads();
            for (int off = 1; off < 1024; off <<= 1) {
                unsigned v = (t + off < 1024) ? s_arr[t + off] : 0u;
                __syncthreads();
                s_arr[t] += v;
                __syncthreads();
            }
            unsigned running = s_arr[t] - a;
#pragma unroll
            for (int jj = C - 1; jj >= 0; --jj) {
                if (running < K && running + h[jj] >= K) {
                    g_B_star = t * C + jj;     // key space: bits>>17
                    g_c_above = running;
                    s_found = 1;
                }
                running += h[jj];
            }
            __syncthreads();
            if (t == 0 && !s_found) { g_B_star = -1; g_c_above = s_arr[0]; }
            __syncthreads();

            int B = g_B_star;
            for (int i = t; i < n4; i += 1024) {
                float4 v = x4[i];
                float vals[4] = {v.x, v.y, v.z, v.w};
#pragma unroll
                for (int j = 0; j < 4; j++) {
                    float val = vals[j];
                    if (val > 0.0f) {
                        unsigned u = __float_as_uint(val);
                        int bin = (int)(u >> 17);
                        if (bin > B) {
                            out[4 * i + j] = val;
                        } else if (bin == B) {
                            unsigned p = atomicAdd(&g_nb, 1u);
                            if (p < BND_CAP) { g_bnd_bits[p] = u; g_bnd_idx[p] = (unsigned)(4 * i + j); }
                        }
                    }
                }
            }
            __syncthreads();
            sel2_body(out, false, 17);
            __syncthreads();
            for (int i = t; i < NBINS; i += 1024) g_hist2[i] = 0u;
        }
    } else {
        sel2_body(out, true, 11);
        __syncthreads();
    }
    // ---- self-cleaning for the next graph replay ----
    for (int i = t; i < NBINS_HI; i += 1024) g_hist_hi[i] = 0u;
    if (t < 512) gh1[t] = 0u;
    if (t == 0) { g_nb = 0u; g_c8 = 0u; }
}

extern "C" void kernel_launch(void* const* d_in, const int* in_sizes, int n_in,
                              void* d_out, int out_size) {
    const float* x    = (const float*)d_in[0];
    const int*   kptr = (const int*)d_in[1];
    float*       out  = (float*)d_out;
    int n  = in_sizes[0];
    int n4 = n >> 2;

    int ntiles = (n4 + 255) / 256;
    int main_blocks = (ntiles + 31) / 32;
    if (main_blocks > NUM_WARPS / 32) main_blocks = NUM_WARPS / 32;
    int nwarps = main_blocks * 32;

    k_main<<<main_blocks, 1024>>>((const float4*)x, (float4*)out, n4, ntiles);
    k_scan<<<1, 1024>>>(kptr, n);
    k_scatter<<<512, 1024>>>(out, nwarps);
    k_refine<<<1, 1024>>>((const float4*)x, out, n4);
}

// round 16
// speedup vs baseline: 1.3256x; 1.0025x over previous
#include <cuda_runtime.h>
#include <cstdint>

// ---------------------------------------------------------------------------
// BatchTopK via exact threshold selection on float bit patterns. 4 kernels:
//   k_main:    proven streaming loop (byte-frozen): read x, out=0, detect
//              >= 3.0, candidates -> per-warp global slabs + SMEM hist in the
//              rare branch. Hist: 8192 fine bins over [2.0,8.0) (bits>>11)
//              + c8 counter for >= 8.0.
//   k_scan:    1 block, shfl suffix scan (seeded with c8) -> B*, c_above,
//              k_total; need_full if threshold outside [2,8) coverage.
//   k_scatter: slab walk (parallel loads, 1 slot/thread): bin>B* -> out,
//              boundary -> buffer (+ inline 256-bin level-1 hist gh1).
//              Also grid-parallel self-clean of g_hist_hi.
//   k_refine:  1 block: exact threshold bits (shift-parameterized two-level
//              refinement); ties kept by smallest index via O(tcnt^2) rank
//              selection. Guarded exact full-range fallback (bits>>17 keys).
//              Cleans only tiny state (gh1, g_nb, g_c8).
// No __threadfence / tickets; no global atomics in k_main's hot path.
// ---------------------------------------------------------------------------

#define T_DET      3.0f
#define NBINS_HI   8192     // fine bins: (bits>>11) - 0x80000, range [2.0,8.0)
#define BIN_BASE   0x80000u // 0x40000000 >> 11
#define BITS_8     0x41000000u
#define NBINS      16384    // fallback bins: bits>>17 over all positives
#define SLAB       16
#define NUM_WARPS  65536
#define BND_CAP    (1u << 20)
#define TIE_CAP    4096

__device__ unsigned g_hist_hi[NBINS_HI];
__device__ unsigned g_hist2[NBINS];     // fallback only
__device__ unsigned gh1[512];           // level-1 refinement hist
__device__ unsigned g_c8;               // count of candidates >= 8.0
__device__ int      g_B_star;           // key (bits>>11), or bits>>17 in fallback
__device__ unsigned g_c_above;
__device__ unsigned g_k_total;
__device__ int      g_need_full;
__device__ unsigned g_nb;
__device__ unsigned g_warp_cnt[NUM_WARPS];
__device__ uint2    g_cand[(size_t)NUM_WARPS * SLAB];
__device__ unsigned g_bnd_bits[BND_CAP];
__device__ unsigned g_bnd_idx[BND_CAP];

__device__ __forceinline__ void handle4(float4 a, int i4, unsigned* sh,
                                        unsigned* sc8, unsigned* wctr, uint2* slab) {
    float vals[4] = {a.x, a.y, a.z, a.w};
#pragma unroll
    for (int j = 0; j < 4; j++) {
        if (vals[j] >= T_DET) {
            unsigned u = __float_as_uint(vals[j]);
            if (u < BITS_8) atomicAdd(&sh[(u >> 11) - BIN_BASE], 1u);
            else            atomicAdd(sc8, 1u);
            unsigned pos = atomicAdd(wctr, 1u);
            if (pos < SLAB) slab[pos] = make_uint2(u, (unsigned)(4 * i4 + j));
        }
    }
}

// Proven streaming loop + branch-only smem hist (UNCHANGED).
__global__ void __launch_bounds__(1024, 1)
k_main(const float4* __restrict__ x4, float4* __restrict__ o4, int n4, int ntiles) {
    __shared__ unsigned sh[NBINS_HI];
    __shared__ unsigned wcnt[32];
    __shared__ unsigned s_c8;
    for (int b = threadIdx.x; b < NBINS_HI; b += 1024) sh[b] = 0u;
    if (threadIdx.x < 32) wcnt[threadIdx.x] = 0u;
    if (threadIdx.x == 0) s_c8 = 0u;
    __syncthreads();

    const int lane   = threadIdx.x & 31;
    const int wlocal = threadIdx.x >> 5;
    const int W      = blockIdx.x * 32 + wlocal;
    const int NW     = gridDim.x * 32;
    uint2*    slab   = g_cand + (size_t)W * SLAB;
    unsigned* wctr   = &wcnt[wlocal];
    const float4 z4  = make_float4(0.f, 0.f, 0.f, 0.f);

    for (int tile = W; tile < ntiles; tile += NW) {
        const int base = tile * 256;
        if (base + 256 <= n4) {
            float4 v[8];
#pragma unroll
            for (int it = 0; it < 8; it++) v[it] = x4[base + it * 32 + lane];
#pragma unroll
            for (int it = 0; it < 8; it++) o4[base + it * 32 + lane] = z4;
#pragma unroll
            for (int p = 0; p < 4; p++) {
                float4 a = v[2 * p], b = v[2 * p + 1];
                float m = fmaxf(fmaxf(fmaxf(a.x, a.y), fmaxf(a.z, a.w)),
                                fmaxf(fmaxf(b.x, b.y), fmaxf(b.z, b.w)));
                if (m >= T_DET) {
                    handle4(a, base + (2 * p) * 32 + lane, sh, &s_c8, wctr, slab);
                    handle4(b, base + (2 * p + 1) * 32 + lane, sh, &s_c8, wctr, slab);
                }
            }
        } else {
            for (int it = 0; it < 8; it++) {
                int i4 = base + it * 32 + lane;
                if (i4 < n4) {
                    float4 a = x4[i4];
                    o4[i4] = z4;
                    handle4(a, i4, sh, &s_c8, wctr, slab);
                }
            }
        }
    }
    __syncwarp();
    if (lane == 0) g_warp_cnt[W] = wcnt[wlocal];

    __syncthreads();
    for (int b = threadIdx.x; b < NBINS_HI; b += 1024) {
        unsigned c = sh[b];
        if (c) atomicAdd(&g_hist_hi[b], c);
    }
    if (threadIdx.x == 0 && s_c8) atomicAdd(&g_c8, s_c8);
}

// Single block, shfl suffix scan over 8192 fine bins -> threshold bin.
__global__ void __launch_bounds__(1024, 1)
k_scan(const int* __restrict__ kptr, int n) {
    __shared__ unsigned wtot[32];
    __shared__ unsigned wexc[32];
    __shared__ int s_any;
    int t = threadIdx.x, lane = t & 31, wid = t >> 5;

    unsigned batch = (unsigned)(n >> 16);   // d_sae = 65536
    unsigned K = (unsigned)(*kptr) * batch;
    unsigned c8 = g_c8;                      // candidates >= 8.0 (above range)
    if (t == 0) { g_k_total = K; s_any = 0; }

    const int C = NBINS_HI / 1024;   // 8
    unsigned h[C];
    unsigned a = 0;
#pragma unroll
    for (int jj = 0; jj < C; jj++) { h[jj] = g_hist_hi[t * C + jj]; a += h[jj]; }

    unsigned x = a;
#pragma unroll
    for (int off = 1; off < 32; off <<= 1) {
        unsigned y = __shfl_down_sync(0xFFFFFFFFu, x, off);
        if (lane + off < 32) x += y;
    }
    if (lane == 0) wtot[wid] = x;
    __syncthreads();
    if (wid == 0) {
        unsigned w = wtot[lane];
        unsigned xs = w;
#pragma unroll
        for (int off = 1; off < 32; off <<= 1) {
            unsigned y = __shfl_down_sync(0xFFFFFFFFu, xs, off);
            if (lane + off < 32) xs += y;
        }
        wexc[lane] = xs - w;
    }
    __syncthreads();

    unsigned running = (x + wexc[wid]) - a + c8;   // seed with >=8.0 count
    int found = 0;
#pragma unroll
    for (int jj = C - 1; jj >= 0; --jj) {
        if (running < K && running + h[jj] >= K) {
            g_B_star = (int)(BIN_BASE + (unsigned)(t * C + jj));  // absolute key
            g_c_above = running;
            found = 1;
        }
        running += h[jj];
    }
    if (found) s_any = 1;
    __syncthreads();
    if (t == 0) g_need_full = !s_any;
}

// Slab walk (parallel loads): winners -> out; boundary -> buffer + gh1.
// Also grid-parallel self-clean of g_hist_hi (consumed only by k_scan, done).
__global__ void __launch_bounds__(1024, 1)
k_scatter(float* __restrict__ out, int nwarps) {
    {
        int gstride = gridDim.x * blockDim.x;
        for (int i = blockIdx.x * blockDim.x + threadIdx.x; i < NBINS_HI; i += gstride)
            g_hist_hi[i] = 0u;
    }
    if (g_need_full) return;
    const int B = g_B_star;                  // key space: bits>>11
    int nslots = nwarps * SLAB;
    int stride = gridDim.x * blockDim.x;
    for (int s = blockIdx.x * blockDim.x + threadIdx.x; s < nslots; s += stride) {
        int w = s >> 4;                       // SLAB == 16
        int e = s & 15;
        unsigned cnt = g_warp_cnt[w];
        uint2 c = g_cand[s];
        if (e == 0 && cnt > SLAB) g_need_full = 1;
        if ((unsigned)e < min(cnt, (unsigned)SLAB)) {
            int bin = (int)(c.x >> 11);
            if (bin > B) {
                out[c.y] = __uint_as_float(c.x);
            } else if (bin == B) {
                unsigned p = atomicAdd(&g_nb, 1u);
                if (p < BND_CAP) {
                    g_bnd_bits[p] = c.x; g_bnd_idx[p] = c.y;
                    atomicAdd(&gh1[(c.x >> 3) & 0xFFu], 1u);   // bits[10:3]
                } else g_need_full = 1;
            }
        }
    }
}

// Low-barrier crossing-finder over NB (<=1024) bins in s_h.
__device__ void find_cross(const unsigned* s_h, int NB, unsigned m,
                           int* o_bin, unsigned* o_above) {
    __shared__ unsigned wtot[32];
    __shared__ unsigned wexc[32];
    int t = threadIdx.x, lane = t & 31, wid = t >> 5;
    unsigned a = (t < NB) ? s_h[t] : 0u;
    unsigned x = a;
#pragma unroll
    for (int off = 1; off < 32; off <<= 1) {
        unsigned y = __shfl_down_sync(0xFFFFFFFFu, x, off);
        if (lane + off < 32) x += y;
    }
    if (lane == 0 && wid < 32) wtot[wid] = (t < NB) ? x : 0u;
    __syncthreads();
    if (wid == 0) {
        unsigned w = wtot[lane];
        unsigned xs = w;
#pragma unroll
        for (int off = 1; off < 32; off <<= 1) {
            unsigned y = __shfl_down_sync(0xFFFFFFFFu, xs, off);
            if (lane + off < 32) xs += y;
        }
        wexc[lane] = xs - w;
    }
    __syncthreads();
    if (t < NB) {
        unsigned incl = x + wexc[wid];
        unsigned above = incl - a;
        if (above < m && incl >= m) { *o_bin = t; *o_above = above; }
    }
    __syncthreads();
}

// Block-wide refine+tie over the boundary buffer. Key = bits>>S.
__device__ void sel2_body(float* __restrict__ out, bool use_gh1, int S) {
    __shared__ unsigned h1[256];
    __shared__ unsigned h2[512];
    __shared__ unsigned tie_idx[TIE_CAP];
    __shared__ unsigned s_tcnt;
    __shared__ int s_s1;
    __shared__ unsigned s_c1;
    __shared__ int s_b2;
    __shared__ unsigned s_c2;
    __shared__ int s_mode;

    int t = threadIdx.x;
    unsigned nb = min(g_nb, (unsigned)BND_CAP);
    int B = g_B_star;
    unsigned K = g_k_total, ca = g_c_above;
    const int S2 = S - 8;
    const int NB2 = 1 << S2;
    const unsigned M2 = (unsigned)NB2 - 1u;

    if (t == 0) {
        if (nb == 0u || ca >= K) s_mode = 2;
        else s_mode = ((K - ca) >= nb) ? 1 : 0;
    }
    __syncthreads();
    if (s_mode == 2) return;
    if (s_mode == 1) {
        for (unsigned i = t; i < nb; i += blockDim.x)
            out[g_bnd_idx[i]] = __uint_as_float(g_bnd_bits[i]);
        return;
    }
    unsigned m = K - ca;

    if (use_gh1) {
        if (t < 256) h1[t] = gh1[t];
        __syncthreads();
    } else {
        if (t < 256) h1[t] = 0u;
        __syncthreads();
        for (unsigned i = t; i < nb; i += blockDim.x)
            atomicAdd(&h1[(g_bnd_bits[i] >> S2) & 0xFFu], 1u);
        __syncthreads();
    }
    find_cross(h1, 256, m, &s_s1, &s_c1);
    int s1 = s_s1; unsigned c1 = s_c1;

    if (t < NB2) h2[t] = 0u;
    __syncthreads();
    for (unsigned i = t; i < nb; i += blockDim.x) {
        unsigned bits = g_bnd_bits[i];
        if (((bits >> S2) & 0xFFu) == (unsigned)s1)
            atomicAdd(&h2[bits & M2], 1u);
    }
    __syncthreads();
    find_cross(h2, NB2, m - c1, &s_b2, &s_c2);
    unsigned Tb = ((unsigned)B << S) | ((unsigned)s1 << S2) | (unsigned)s_b2;
    unsigned r  = (m - c1) - s_c2;
    if (t == 0) s_tcnt = 0u;
    __syncthreads();

    for (unsigned i = t; i < nb; i += blockDim.x) {
        unsigned bits = g_bnd_bits[i];
        if (bits > Tb) {
            out[g_bnd_idx[i]] = __uint_as_float(bits);
        } else if (bits == Tb) {
            unsigned p = atomicAdd(&s_tcnt, 1u);
            if (p < TIE_CAP) tie_idx[p] = g_bnd_idx[i];
        }
    }
    __syncthreads();
    unsigned tcnt = min(s_tcnt, (unsigned)TIE_CAP);
    if (r >= tcnt) {
        for (unsigned i = t; i < tcnt; i += blockDim.x)
            out[tie_idx[i]] = __uint_as_float(Tb);
        return;
    }
    // keep the r smallest indices among tcnt ties (O(tcnt^2), tcnt tiny)
    for (unsigned i = t; i < tcnt; i += blockDim.x) {
        unsigned my = tie_idx[i];
        unsigned rank = 0;
        for (unsigned j2 = 0; j2 < tcnt; j2++)
            rank += (tie_idx[j2] < my) ? 1u : 0u;
        if (rank < r) out[my] = __uint_as_float(Tb);
    }
}

// Single block: refinement (or guarded exact fallback), then tiny cleanup.
__global__ void __launch_bounds__(1024, 1)
k_refine(const float4* __restrict__ x4, float* __restrict__ out, int n4) {
    int t = threadIdx.x;
    if (g_need_full) {
        unsigned K = g_k_total;
        if (t == 0) g_nb = 0u;   // discard partial boundary entries
        __syncthreads();
        if (K > 0u) {
            for (int i = t; i < n4; i += 1024) {
                float4 v = x4[i];
                float vals[4] = {v.x, v.y, v.z, v.w};
#pragma unroll
                for (int j = 0; j < 4; j++)
                    if (vals[j] > 0.0f)
                        atomicAdd(&g_hist2[__float_as_uint(vals[j]) >> 17], 1u);
            }
            __syncthreads();

            __shared__ unsigned s_arr[1024];
            __shared__ int s_found;
            const int C = NBINS / 1024;
            unsigned h[C];
            unsigned a = 0;
            if (t == 0) s_found = 0;
            __syncthreads();
#pragma unroll
            for (int jj = 0; jj < C; jj++) { h[jj] = g_hist2[t * C + jj]; a += h[jj]; }
            s_arr[t] = a;
            __syncthreads();
            for (int off = 1; off < 1024; off <<= 1) {
                unsigned v = (t + off < 1024) ? s_arr[t + off] : 0u;
                __syncthreads();
                s_arr[t] += v;
                __syncthreads();
            }
            unsigned running = s_arr[t] - a;
#pragma unroll
            for (int jj = C - 1; jj >= 0; --jj) {
                if (running < K && running + h[jj] >= K) {
                    g_B_star = t * C + jj;     // key space: bits>>17
                    g_c_above = running;
                    s_found = 1;
                }
                running += h[jj];
            }
            __syncthreads();
            if (t == 0 && !s_found) { g_B_star = -1; g_c_above = s_arr[0]; }
            __syncthreads();

            int B = g_B_star;
            for (int i = t; i < n4; i += 1024) {
                float4 v = x4[i];
                float vals[4] = {v.x, v.y, v.z, v.w};
#pragma unroll
                for (int j = 0; j < 4; j++) {
                    float val = vals[j];
                    if (val > 0.0f) {
                        unsigned u = __float_as_uint(val);
                        int bin = (int)(u >> 17);
                        if (bin > B) {
                            out[4 * i + j] = val;
                        } else if (bin == B) {
                            unsigned p = atomicAdd(&g_nb, 1u);
                            if (p < BND_CAP) { g_bnd_bits[p] = u; g_bnd_idx[p] = (unsigned)(4 * i + j); }
                        }
                    }
                }
            }
            __syncthreads();
            sel2_body(out, false, 17);
            __syncthreads();
            for (int i = t; i < NBINS; i += 1024) g_hist2[i] = 0u;
        }
    } else {
        sel2_body(out, true, 11);
        __syncthreads();
    }
    // ---- self-cleaning for the next graph replay (tiny state only) ----
    if (t < 512) gh1[t] = 0u;
    if (t == 0) { g_nb = 0u; g_c8 = 0u; }
}

extern "C" void kernel_launch(void* const* d_in, const int* in_sizes, int n_in,
                              void* d_out, int out_size) {
    const float* x    = (const float*)d_in[0];
    const int*   kptr = (const int*)d_in[1];
    float*       out  = (float*)d_out;
    int n  = in_sizes[0];
    int n4 = n >> 2;

    int ntiles = (n4 + 255) / 256;
    int main_blocks = (ntiles + 31) / 32;
    if (main_blocks > NUM_WARPS / 32) main_blocks = NUM_WARPS / 32;
    int nwarps = main_blocks * 32;

    k_main<<<main_blocks, 1024>>>((const float4*)x, (float4*)out, n4, ntiles);
    k_scan<<<1, 1024>>>(kptr, n);
    k_scatter<<<1024, 1024>>>(out, nwarps);
    k_refine<<<1, 1024>>>((const float4*)x, out, n4);
}